// round 16
// baseline (speedup 1.0000x reference)
#include <cuda_runtime.h>
#include <cuda_fp16.h>
#include <math.h>
#include <float.h>
#include <stdint.h>

// Problem constants
#define BB    32
#define NNODE 256
#define DD    512
#define HH    8
#define EE    1024
#define EDIM  256
#define GDIM  64
#define HDIM  64
#define BNROWS (BB*NNODE)   // 8192
#define DFF   2048

// ---------------- scratch (device globals; no runtime alloc) ----------------
__device__ float g_x2 [BNROWS*DD];
__device__ float g_ebias[BB*EE*HH];
__device__ int   g_wmap[BB*NNODE*NNODE];
__device__ int   g_nbr [BB*NNODE*NNODE];
__device__ int   g_cnt [BB*NNODE];

// fp16 activations + weights
__device__ __half g_q  [BNROWS*DD];
__device__ __half g_k  [BNROWS*DD];
__device__ __half g_v  [BNROWS*DD];
__device__ __half g_xn [BNROWS*DD];
__device__ __half g_att[BNROWS*DD];
__device__ __half g_ln2[BNROWS*DD];
__device__ __half g_h1 [BNROWS*DFF];
__device__ __half g_wq[DD*DD], g_wk[DD*DD], g_wv[DD*DD], g_wo[DD*DD];
__device__ __half g_w1[DFF*DD], g_w2[DD*DFF];

// ---------------- fused fp32 -> fp16 cast over all 6 weight tensors ----------------
struct CastJobs {
    const float4* src[6];
    __half2* dst[6];
    int cum[7];
};

__global__ void cast_all_kernel(CastJobs jobs) {
    int idx = blockIdx.x * 256 + threadIdx.x;
    if (idx >= jobs.cum[6]) return;
    int j = 0;
#pragma unroll
    for (int t = 1; t < 6; t++) j += (idx >= jobs.cum[t]);
    int i = idx - jobs.cum[j];
    float4 v = jobs.src[j][i];
    jobs.dst[j][2 * i]     = __half2(__float2half_rn(v.x), __float2half_rn(v.y));
    jobs.dst[j][2 * i + 1] = __half2(__float2half_rn(v.z), __float2half_rn(v.w));
}

// ---------------- LayerNorm -> fp16 ----------------
__global__ void ln_h_kernel(const float* __restrict__ x, const float* __restrict__ g,
                            const float* __restrict__ b, __half* __restrict__ y) {
    int row = blockIdx.x;
    const float* xr = x + (size_t)row * DD;
    int tid = threadIdx.x; // 128
    float v[4];
    float s = 0.f, s2 = 0.f;
#pragma unroll
    for (int i = 0; i < 4; i++) {
        v[i] = xr[tid + i * 128];
        s += v[i]; s2 += v[i] * v[i];
    }
    __shared__ float rs[4], rs2[4];
    for (int o = 16; o; o >>= 1) {
        s  += __shfl_xor_sync(~0u, s,  o);
        s2 += __shfl_xor_sync(~0u, s2, o);
    }
    int w = tid >> 5;
    if ((tid & 31) == 0) { rs[w] = s; rs2[w] = s2; }
    __syncthreads();
    s  = rs[0] + rs[1] + rs[2] + rs[3];
    s2 = rs2[0] + rs2[1] + rs2[2] + rs2[3];
    float mean = s * (1.f / DD);
    float var  = s2 * (1.f / DD) - mean * mean;
    float r = rsqrtf(var + 1e-5f);
#pragma unroll
    for (int i = 0; i < 4; i++) {
        int c = tid + i * 128;
        float yv = (v[i] - mean) * r * g[c] + b[c];
        y[(size_t)row * DD + c] = __float2half_rn(yv);
    }
}

// ========== fp16 GEMM: 256 thr, 8 warps 4x2, 2-stage x K64 chunks, 2 CTA/SM ==========
#define PITCH 72    // fp16 per smem row (64 data + 8 pad) = 144 B
#define ROWB  144
#define GSTAGE 36864          // (128 A rows + 128 B rows) * 144 B
#define BOFF   18432          // B array offset within stage
#define GSMEMB (2*GSTAGE)

#define CP16(dst, src) \
    asm volatile("cp.async.cg.shared.global [%0], [%1], 16;" :: "r"(dst), "l"(src))

__device__ __forceinline__ void ldsm4(uint32_t a, uint32_t& r0, uint32_t& r1,
                                      uint32_t& r2, uint32_t& r3) {
    asm volatile("ldmatrix.sync.aligned.m8n8.x4.shared.b16 {%0,%1,%2,%3}, [%4];"
                 : "=r"(r0), "=r"(r1), "=r"(r2), "=r"(r3) : "r"(a));
}

__device__ __forceinline__ void mma16816(float (&d)[4], const uint32_t (&a)[4],
                                         const uint32_t* b) {
    asm volatile("mma.sync.aligned.m16n8k16.row.col.f32.f16.f16.f32 "
                 "{%0,%1,%2,%3}, {%4,%5,%6,%7}, {%8,%9}, {%0,%1,%2,%3};"
                 : "+f"(d[0]), "+f"(d[1]), "+f"(d[2]), "+f"(d[3])
                 : "r"(a[0]), "r"(a[1]), "r"(a[2]), "r"(a[3]), "r"(b[0]), "r"(b[1]));
}

// EPI: 0=bias->f32, 1=+res->f32, 2=silu->fp16, 3=+res,*rowscale->f32, 4=bias->fp16
template<int EPI>
__device__ __forceinline__ void gemm_body(
        const __half* __restrict__ A_g, const __half* __restrict__ B_g,
        const float* __restrict__ bias, const float* __restrict__ res,
        const float* __restrict__ rowscale, float* __restrict__ C,
        __half* __restrict__ Ch,
        int M, int Nout, int K, int bm0, int bn0) {
    extern __shared__ __align__(16) __half sm[];
    uint32_t smBase = (uint32_t)__cvta_generic_to_shared(sm);

    int tid = threadIdx.x;               // 256 = 8 warps (4x2)
    int warp = tid >> 5, lane = tid & 31;
    int wm = warp >> 1, wn = warp & 1;

    float acc[2][8][4];
#pragma unroll
    for (int i = 0; i < 2; i++)
#pragma unroll
        for (int j = 0; j < 8; j++)
#pragma unroll
            for (int r = 0; r < 4; r++) acc[i][j][r] = 0.f;

    int a_r  = lane & 15;
    int a_cb = (lane >> 4) << 4;
    uint32_t aOffH = (uint32_t)((wm * 32 + a_r) * ROWB + a_cb);
    int b_r  = ((lane >> 4) & 1) * 8 + (lane & 7);
    int b_cb = ((lane >> 3) & 1) << 4;
    uint32_t bOffH = (uint32_t)((wn * 64 + b_r) * ROWB + b_cb);

    auto issue_tile = [&](int s, int k0) {
        uint32_t st = smBase + (uint32_t)s * (uint32_t)GSTAGE;
#pragma unroll
        for (int i = 0; i < 4; i++) {
            int c = tid + i * 256;           // 0..1023: row=c>>3, chunk=(c&7)
            int row = c >> 3;
            int cb  = (c & 7) << 4;
            uint32_t so = (uint32_t)(row * ROWB + cb);
            size_t ga = (size_t)(bm0 + row) * K + k0 + (c & 7) * 8;
            size_t gb = (size_t)(bn0 + row) * K + k0 + (c & 7) * 8;
            CP16(st + so,        A_g + ga);
            CP16(st + BOFF + so, B_g + gb);
        }
    };

    issue_tile(0, 0);
    asm volatile("cp.async.commit_group;");
    issue_tile(1, 64);
    asm volatile("cp.async.commit_group;");

    int ktiles = K >> 6;
#pragma unroll 1
    for (int t = 0; t < ktiles; t++) {
        int s = t & 1;
        asm volatile("cp.async.wait_group 1;");
        __syncthreads();

        uint32_t pA = smBase + (uint32_t)s * (uint32_t)GSTAGE;
        uint32_t pB = pA + (uint32_t)BOFF;
#pragma unroll
        for (int ks = 0; ks < 4; ks++) {
            uint32_t kb = (uint32_t)(ks * 32);
            uint32_t ah[2][4];
#pragma unroll
            for (int mi = 0; mi < 2; mi++) {
                uint32_t off = aOffH + (uint32_t)(mi * 16 * ROWB) + kb;
                ldsm4(pA + off, ah[mi][0], ah[mi][1], ah[mi][2], ah[mi][3]);
            }
#pragma unroll
            for (int bp = 0; bp < 4; bp++) {
                uint32_t off = bOffH + (uint32_t)(bp * 16 * ROWB) + kb;
                uint32_t bh[2][2];
                ldsm4(pB + off, bh[0][0], bh[0][1], bh[1][0], bh[1][1]);
#pragma unroll
                for (int mi = 0; mi < 2; mi++)
#pragma unroll
                    for (int q = 0; q < 2; q++)
                        mma16816(acc[mi][2 * bp + q], ah[mi], bh[q]);
            }
        }
        __syncthreads();
        int nk = (t + 2) << 6;
        if (nk < K) issue_tile(s, nk);
        asm volatile("cp.async.commit_group;");
    }

    // epilogue
    int qr = lane >> 2, qc = (lane & 3) << 1;
#pragma unroll
    for (int mi = 0; mi < 2; mi++) {
        int m0 = bm0 + wm * 32 + mi * 16 + qr;
#pragma unroll
        for (int ni = 0; ni < 8; ni++) {
            int n = bn0 + wn * 64 + ni * 8 + qc;
            float b0 = bias[n], b1 = bias[n + 1];
#pragma unroll
            for (int rr = 0; rr < 2; rr++) {
                int m = m0 + rr * 8;
                float v0 = acc[mi][ni][rr * 2 + 0] + b0;
                float v1 = acc[mi][ni][rr * 2 + 1] + b1;
                if (EPI == 1 || EPI == 3) {
                    v0 += res[(size_t)m * Nout + n];
                    v1 += res[(size_t)m * Nout + n + 1];
                }
                if (EPI == 2) {
                    v0 = v0 / (1.f + expf(-v0));
                    v1 = v1 / (1.f + expf(-v1));
                }
                if (EPI == 2 || EPI == 4) {
                    *(__half2*)(Ch + (size_t)m * Nout + n) =
                        __half2(__float2half_rn(v0), __float2half_rn(v1));
                } else {
                    if (EPI == 3) { float rsc = rowscale[m]; v0 *= rsc; v1 *= rsc; }
                    *(float2*)(C + (size_t)m * Nout + n) = make_float2(v0, v1);
                }
            }
        }
    }
}

template<int EPI>
__global__ void __launch_bounds__(256, 2)
gemm_h(const __half* __restrict__ A_g, const __half* __restrict__ B_g,
       const float* __restrict__ bias, const float* __restrict__ res,
       const float* __restrict__ rowscale, float* __restrict__ C,
       __half* __restrict__ Ch, int M, int Nout, int K) {
    gemm_body<EPI>(A_g, B_g, bias, res, rowscale, C, Ch,
                   M, Nout, K, blockIdx.y * 128, blockIdx.x * 128);
}

// fused QKV (fp16 out): grid (12, 64)
__global__ void __launch_bounds__(256, 2)
gemm_qkv(const __half* __restrict__ A_g,
         const __half* __restrict__ wq, const __half* __restrict__ wk,
         const __half* __restrict__ wv,
         const float* __restrict__ bq, const float* __restrict__ bk,
         const float* __restrict__ bv,
         __half* __restrict__ q, __half* __restrict__ k, __half* __restrict__ v) {
    int wsel = blockIdx.x >> 2;
    int bn0  = (blockIdx.x & 3) * 128;
    const __half* B;
    const float* bias;
    __half* C;
    if (wsel == 0)      { B = wq; bias = bq; C = q; }
    else if (wsel == 1) { B = wk; bias = bk; C = k; }
    else                { B = wv; bias = bv; C = v; }
    gemm_body<4>(A_g, B, bias, nullptr, nullptr, nullptr, C,
                 BNROWS, DD, DD, blockIdx.y * 128, bn0);
}

// ---------------- Edge bias: one warp per (b,e) ----------------
__global__ void edge_bias_kernel(const float* __restrict__ rel, const float* __restrict__ geo,
                                 const float* __restrict__ W_eb, const float* __restrict__ b_eb,
                                 const float* __restrict__ geog, const float* __restrict__ geob,
                                 const float* __restrict__ W_geo, const float* __restrict__ b_geo) {
    int warp = (blockIdx.x * blockDim.x + threadIdx.x) >> 5;
    int lane = threadIdx.x & 31;
    if (warp >= BB * EE) return;
    const float* re = rel + (size_t)warp * EDIM;
    const float* ge = geo + (size_t)warp * GDIM;
    float acc[8] = {0, 0, 0, 0, 0, 0, 0, 0};
#pragma unroll
    for (int it = 0; it < 8; it++) {
        int c = (it << 5) + lane;
        float xv = re[c];
#pragma unroll
        for (int h = 0; h < 8; h++) acc[h] += xv * W_eb[h * EDIM + c];
    }
    float g0 = ge[lane], g1 = ge[lane + 32];
    float s = g0 + g1, s2 = g0 * g0 + g1 * g1;
    for (int o = 16; o; o >>= 1) {
        s  += __shfl_xor_sync(~0u, s,  o);
        s2 += __shfl_xor_sync(~0u, s2, o);
    }
    float mean = s * (1.f / 64.f);
    float var  = s2 * (1.f / 64.f) - mean * mean;
    float r = rsqrtf(var + 1e-5f);
    float n0 = (g0 - mean) * r * geog[lane]      + geob[lane];
    float n1 = (g1 - mean) * r * geog[lane + 32] + geob[lane + 32];
#pragma unroll
    for (int h = 0; h < 8; h++)
        acc[h] += n0 * W_geo[h * GDIM + lane] + n1 * W_geo[h * GDIM + lane + 32];
#pragma unroll
    for (int h = 0; h < 8; h++) {
        float v = acc[h];
        for (int o = 16; o; o >>= 1) v += __shfl_xor_sync(~0u, v, o);
        if (lane == h) g_ebias[(size_t)warp * HH + h] = v + b_eb[h] + b_geo[h];
    }
}

// ---------------- winner map + scatter ----------------
__global__ void wmap_init_kernel() {
    int idx = blockIdx.x * 256 + threadIdx.x;
    g_wmap[idx] = -1;
}

__global__ void wmap_scatter_kernel(const int* __restrict__ edges, const float* __restrict__ emask) {
    int t = blockIdx.x * 256 + threadIdx.x;
    if (t >= BB * EE) return;
    int b = t >> 10, e = t & 1023;
    if (emask[t] > 0.5f) {
        int s = min(max(edges[2 * t], 0), NNODE - 1);
        int d = min(max(edges[2 * t + 1], 0), NNODE - 1);
        atomicMax(&g_wmap[b * 65536 + s * 256 + d], e);
        atomicMax(&g_wmap[b * 65536 + d * 256 + s], e + EE);
    }
}

// ---------------- neighbor-list compaction: one warp per (b,i) ----------------
__global__ void nbr_kernel(const float* __restrict__ nmask) {
    int gw = (blockIdx.x * blockDim.x + threadIdx.x) >> 5;
    int lane = threadIdx.x & 31;
    if (gw >= BB * NNODE) return;
    int b = gw >> 8, i = gw & 255;
    if (nmask[gw] == 0.f) {
        if (lane == 0) g_cnt[gw] = 0;
        return;
    }
    const int* wrow = g_wmap + (size_t)gw * 256;
    int* nrow = g_nbr + (size_t)gw * 256;
    int base = 0;
#pragma unroll
    for (int c = 0; c < 8; c++) {
        int j = c * 32 + lane;
        int w = wrow[j];
        bool valid = ((w >= 0) || (j == i)) && (nmask[b * 256 + j] != 0.f);
        unsigned m = __ballot_sync(~0u, valid);
        if (valid) {
            int pos = base + __popc(m & ((1u << lane) - 1));
            nrow[pos] = ((w + 1) << 8) | j;
        }
        base += __popc(m);
    }
    if (lane == 0) g_cnt[gw] = base;
}

// ---------------- sparse attention (fp16 q/k/v): block per (b,i), warp per head ----------------
__global__ void __launch_bounds__(256)
attn_sparse_kernel() {
    __shared__ float sc[HH][NNODE];
    __shared__ float qs[HH][64];

    int bi = blockIdx.x;
    int b = bi >> 8;
    int tid = threadIdx.x, h = tid >> 5, lane = tid & 31;
    size_t orow = (size_t)bi * DD + h * HDIM;

    int cnt = g_cnt[bi];
    int d0 = lane << 1;
    if (cnt == 0) {
        *(__half2*)&g_att[orow + d0] = __half2(__float2half_rn(0.f), __float2half_rn(0.f));
        return;
    }

    qs[h][lane]      = __half2float(g_q[orow + lane]);
    qs[h][lane + 32] = __half2float(g_q[orow + lane + 32]);
    __syncwarp();

    const int* nrow = g_nbr + (size_t)bi * 256;
    const float* qh = qs[h];

    float mx = -FLT_MAX;
    for (int c0 = 0; c0 < cnt; c0 += 32) {
        int idx = c0 + lane;
        float s = -FLT_MAX;
        if (idx < cnt) {
            int packed = nrow[idx];
            int j = packed & 255;
            int w = (packed >> 8) - 1;
            const __half2* kr = (const __half2*)(g_k + (size_t)(b * NNODE + j) * DD + h * HDIM);
            float a = 0.f;
#pragma unroll
            for (int d2 = 0; d2 < 32; d2++) {
                float2 kv = __half22float2(kr[d2]);
                a += kv.x * qh[2 * d2] + kv.y * qh[2 * d2 + 1];
            }
            float bias = 0.f;
            if (w >= 0) {
                int e = (w >= EE) ? w - EE : w;
                bias = g_ebias[((size_t)b * EE + e) * HH + h];
            }
            s = a * 0.125f + bias;
            sc[h][idx] = s;
        }
        mx = fmaxf(mx, s);
    }
    for (int o = 16; o; o >>= 1) mx = fmaxf(mx, __shfl_xor_sync(~0u, mx, o));

    float sum = 0.f;
    for (int c0 = 0; c0 < cnt; c0 += 32) {
        int idx = c0 + lane;
        if (idx < cnt) {
            float p = expf(sc[h][idx] - mx);
            sc[h][idx] = p;
            sum += p;
        }
    }
    for (int o = 16; o; o >>= 1) sum += __shfl_xor_sync(~0u, sum, o);
    float inv = 1.f / sum;
    __syncwarp();

    float o0 = 0.f, o1 = 0.f;
    for (int idx = 0; idx < cnt; idx++) {
        int j = nrow[idx] & 255;
        float p = sc[h][idx];
        float2 vv = __half22float2(
            *(const __half2*)(g_v + (size_t)(b * NNODE + j) * DD + h * HDIM + d0));
        o0 += p * vv.x;
        o1 += p * vv.y;
    }
    o0 *= inv; o1 *= inv;
    *(__half2*)&g_att[orow + d0] = __half2(__float2half_rn(o0), __float2half_rn(o1));
}

// ---------------- host launcher ----------------
extern "C" void kernel_launch(void* const* d_in, const int* in_sizes, int n_in,
                              void* d_out, int out_size) {
    const float* x     = (const float*)d_in[0];
    const float* nmask = (const float*)d_in[1];
    const int*   edges = (const int*)  d_in[2];
    const float* emask = (const float*)d_in[3];
    const float* rel   = (const float*)d_in[4];
    const float* geo   = (const float*)d_in[5];
    const float* Wq = (const float*)d_in[6];  const float* bq = (const float*)d_in[7];
    const float* Wk = (const float*)d_in[8];  const float* bk = (const float*)d_in[9];
    const float* Wv = (const float*)d_in[10]; const float* bv = (const float*)d_in[11];
    const float* W_eb = (const float*)d_in[12]; const float* b_eb = (const float*)d_in[13];
    const float* geog = (const float*)d_in[14]; const float* geob = (const float*)d_in[15];
    const float* W_geo = (const float*)d_in[16]; const float* b_geo = (const float*)d_in[17];
    const float* W_out = (const float*)d_in[18]; const float* b_out = (const float*)d_in[19];
    const float* ng = (const float*)d_in[20]; const float* nb = (const float*)d_in[21];
    const float* fg = (const float*)d_in[22]; const float* fb = (const float*)d_in[23];
    const float* W1 = (const float*)d_in[24]; const float* b1 = (const float*)d_in[25];
    const float* W2 = (const float*)d_in[26]; const float* b2 = (const float*)d_in[27];
    float* out = (float*)d_out;

    float* px2;
    cudaGetSymbolAddress((void**)&px2, g_x2);
    __half *pq, *pk, *pv, *xn, *att, *ln2, *h1;
    __half *wq, *wk, *wv, *wo, *w1, *w2;
    cudaGetSymbolAddress((void**)&pq,  g_q);
    cudaGetSymbolAddress((void**)&pk,  g_k);
    cudaGetSymbolAddress((void**)&pv,  g_v);
    cudaGetSymbolAddress((void**)&xn,  g_xn);
    cudaGetSymbolAddress((void**)&att, g_att);
    cudaGetSymbolAddress((void**)&ln2, g_ln2);
    cudaGetSymbolAddress((void**)&h1,  g_h1);
    cudaGetSymbolAddress((void**)&wq, g_wq);
    cudaGetSymbolAddress((void**)&wk, g_wk);
    cudaGetSymbolAddress((void**)&wv, g_wv);
    cudaGetSymbolAddress((void**)&wo, g_wo);
    cudaGetSymbolAddress((void**)&w1, g_w1);
    cudaGetSymbolAddress((void**)&w2, g_w2);

    cudaFuncSetAttribute(gemm_qkv,  cudaFuncAttributeMaxDynamicSharedMemorySize, GSMEMB);
    cudaFuncSetAttribute(gemm_h<1>, cudaFuncAttributeMaxDynamicSharedMemorySize, GSMEMB);
    cudaFuncSetAttribute(gemm_h<2>, cudaFuncAttributeMaxDynamicSharedMemorySize, GSMEMB);
    cudaFuncSetAttribute(gemm_h<3>, cudaFuncAttributeMaxDynamicSharedMemorySize, GSMEMB);

    // 0) fused weight casts (one launch)
    CastJobs jobs;
    int wsz = DD * DD / 4, fsz = DFF * DD / 4;
    jobs.src[0] = (const float4*)Wq;    jobs.dst[0] = (__half2*)wq;
    jobs.src[1] = (const float4*)Wk;    jobs.dst[1] = (__half2*)wk;
    jobs.src[2] = (const float4*)Wv;    jobs.dst[2] = (__half2*)wv;
    jobs.src[3] = (const float4*)W_out; jobs.dst[3] = (__half2*)wo;
    jobs.src[4] = (const float4*)W1;    jobs.dst[4] = (__half2*)w1;
    jobs.src[5] = (const float4*)W2;    jobs.dst[5] = (__half2*)w2;
    jobs.cum[0] = 0;
    jobs.cum[1] = wsz;      jobs.cum[2] = 2 * wsz; jobs.cum[3] = 3 * wsz;
    jobs.cum[4] = 4 * wsz;  jobs.cum[5] = 4 * wsz + fsz; jobs.cum[6] = 4 * wsz + 2 * fsz;
    cast_all_kernel<<<(jobs.cum[6] + 255) / 256, 256>>>(jobs);
    // 1) pre-LN -> fp16
    ln_h_kernel<<<BNROWS, 128>>>(x, ng, nb, xn);
    // 2) fused Q,K,V projections (fp16 out)
    gemm_qkv<<<dim3(12, BNROWS / 128), 256, GSMEMB>>>(xn, wq, wk, wv, bq, bk, bv, pq, pk, pv);
    // 3) per-edge bias
    edge_bias_kernel<<<(BB * EE) / 8, 256>>>(rel, geo, W_eb, b_eb, geog, geob, W_geo, b_geo);
    // 4) winner map + neighbor compaction
    wmap_init_kernel<<<(BB * NNODE * NNODE) / 256, 256>>>();
    wmap_scatter_kernel<<<(BB * EE) / 256, 256>>>(edges, emask);
    nbr_kernel<<<(BB * NNODE) / 8, 256>>>(nmask);
    // 5) sparse attention (fp16 in/out)
    attn_sparse_kernel<<<BB * NNODE, 256>>>();
    // 6) output projection + residual
    gemm_h<1><<<dim3(DD / 128, BNROWS / 128), 256, GSMEMB>>>(att, wo, b_out, x, nullptr, px2, nullptr, BNROWS, DD, DD);
    // 7) FF block
    ln_h_kernel<<<BNROWS, 128>>>(px2, fg, fb, ln2);
    gemm_h<2><<<dim3(DFF / 128, BNROWS / 128), 256, GSMEMB>>>(ln2, w1, b1, nullptr, nullptr, nullptr, h1, BNROWS, DFF, DD);
    gemm_h<3><<<dim3(DD / 128, BNROWS / 128), 256, GSMEMB>>>(h1, w2, b2, px2, nmask, out, nullptr, BNROWS, DD, DFF);
}

// round 17
// speedup vs baseline: 1.0206x; 1.0206x over previous
#include <cuda_runtime.h>
#include <cuda_fp16.h>
#include <math.h>
#include <float.h>
#include <stdint.h>

// Problem constants
#define BB    32
#define NNODE 256
#define DD    512
#define HH    8
#define EE    1024
#define EDIM  256
#define GDIM  64
#define HDIM  64
#define BNROWS (BB*NNODE)   // 8192
#define DFF   2048

// ---------------- scratch (device globals; no runtime alloc) ----------------
__device__ float g_q  [BNROWS*DD];
__device__ float g_k  [BNROWS*DD];
__device__ float g_v  [BNROWS*DD];
__device__ float g_x2 [BNROWS*DD];
__device__ float g_ebias[BB*EE*HH];
__device__ int   g_wmap[BB*NNODE*NNODE];
__device__ int   g_nbr [BB*NNODE*NNODE];
__device__ int   g_cnt [BB*NNODE];

// fp16 activations + fp16 weights
__device__ __half g_xn [BNROWS*DD];
__device__ __half g_att[BNROWS*DD];
__device__ __half g_ln2[BNROWS*DD];
__device__ __half g_h1 [BNROWS*DFF];
__device__ __half g_wq[DD*DD], g_wk[DD*DD], g_wv[DD*DD], g_wo[DD*DD];
__device__ __half g_w1[DFF*DD], g_w2[DD*DFF];

// ---------------- fused fp32 -> fp16 cast over all 6 weight tensors ----------------
struct CastJobs {
    const float4* src[6];
    __half2* dst[6];
    int cum[7];
};

__global__ void cast_all_kernel(CastJobs jobs) {
    int idx = blockIdx.x * 256 + threadIdx.x;
    if (idx >= jobs.cum[6]) return;
    int j = 0;
#pragma unroll
    for (int t = 1; t < 6; t++) j += (idx >= jobs.cum[t]);
    int i = idx - jobs.cum[j];
    float4 v = jobs.src[j][i];
    jobs.dst[j][2 * i]     = __half2(__float2half_rn(v.x), __float2half_rn(v.y));
    jobs.dst[j][2 * i + 1] = __half2(__float2half_rn(v.z), __float2half_rn(v.w));
}

// ---------------- LayerNorm -> fp16 ----------------
__global__ void ln_h_kernel(const float* __restrict__ x, const float* __restrict__ g,
                            const float* __restrict__ b, __half* __restrict__ y) {
    int row = blockIdx.x;
    const float* xr = x + (size_t)row * DD;
    int tid = threadIdx.x; // 128
    float v[4];
    float s = 0.f, s2 = 0.f;
#pragma unroll
    for (int i = 0; i < 4; i++) {
        v[i] = xr[tid + i * 128];
        s += v[i]; s2 += v[i] * v[i];
    }
    __shared__ float rs[4], rs2[4];
    for (int o = 16; o; o >>= 1) {
        s  += __shfl_xor_sync(~0u, s,  o);
        s2 += __shfl_xor_sync(~0u, s2, o);
    }
    int w = tid >> 5;
    if ((tid & 31) == 0) { rs[w] = s; rs2[w] = s2; }
    __syncthreads();
    s  = rs[0] + rs[1] + rs[2] + rs[3];
    s2 = rs2[0] + rs2[1] + rs2[2] + rs2[3];
    float mean = s * (1.f / DD);
    float var  = s2 * (1.f / DD) - mean * mean;
    float r = rsqrtf(var + 1e-5f);
#pragma unroll
    for (int i = 0; i < 4; i++) {
        int c = tid + i * 128;
        float yv = (v[i] - mean) * r * g[c] + b[c];
        y[(size_t)row * DD + c] = __float2half_rn(yv);
    }
}

// ========== fp16 tensor-core GEMM (256 thr, 8 warps 4x2, 3-stage K32, 2 CTA/SM) ==========
#define PITCH 40   // fp16 per smem row (32 data + 8 pad) = 80 B
#define GSTAGE 20480
#define GSMEMB (3*GSTAGE)

#define CP16(dst, src) \
    asm volatile("cp.async.cg.shared.global [%0], [%1], 16;" :: "r"(dst), "l"(src))

__device__ __forceinline__ void ldsm4(uint32_t a, uint32_t& r0, uint32_t& r1,
                                      uint32_t& r2, uint32_t& r3) {
    asm volatile("ldmatrix.sync.aligned.m8n8.x4.shared.b16 {%0,%1,%2,%3}, [%4];"
                 : "=r"(r0), "=r"(r1), "=r"(r2), "=r"(r3) : "r"(a));
}

__device__ __forceinline__ void mma16816(float (&d)[4], const uint32_t (&a)[4],
                                         const uint32_t* b) {
    asm volatile("mma.sync.aligned.m16n8k16.row.col.f32.f16.f16.f32 "
                 "{%0,%1,%2,%3}, {%4,%5,%6,%7}, {%8,%9}, {%0,%1,%2,%3};"
                 : "+f"(d[0]), "+f"(d[1]), "+f"(d[2]), "+f"(d[3])
                 : "r"(a[0]), "r"(a[1]), "r"(a[2]), "r"(a[3]), "r"(b[0]), "r"(b[1]));
}

// EPI: 0=bias->f32, 1=+res->f32, 2=silu->fp16, 3=+res,*rowscale->f32
template<int EPI>
__device__ __forceinline__ void gemm_body(
        const __half* __restrict__ A_g, const __half* __restrict__ B_g,
        const float* __restrict__ bias, const float* __restrict__ res,
        const float* __restrict__ rowscale, float* __restrict__ C,
        __half* __restrict__ Ch,
        int M, int Nout, int K, int bm0, int bn0) {
    extern __shared__ __align__(16) __half sm[];
    uint32_t smBase = (uint32_t)__cvta_generic_to_shared(sm);

    int tid = threadIdx.x;               // 256 = 8 warps (4x2)
    int warp = tid >> 5, lane = tid & 31;
    int wm = warp >> 1, wn = warp & 1;

    float acc[2][8][4];
#pragma unroll
    for (int i = 0; i < 2; i++)
#pragma unroll
        for (int j = 0; j < 8; j++)
#pragma unroll
            for (int r = 0; r < 4; r++) acc[i][j][r] = 0.f;

    int row0 = tid >> 2, cc0 = (tid & 3);
    int row1 = row0 + 64;

    int a_r  = lane & 15;
    int a_cb = (lane >> 4) << 4;
    uint32_t aOffH = (uint32_t)((wm * 32 + a_r) * (PITCH * 2) + a_cb);
    int b_r  = ((lane >> 4) & 1) * 8 + (lane & 7);
    int b_cb = ((lane >> 3) & 1) << 4;
    uint32_t bOffH = (uint32_t)((wn * 64 + b_r) * (PITCH * 2) + b_cb);

    auto issue_tile = [&](int s, int k0) {
        uint32_t st = smBase + (uint32_t)s * (uint32_t)GSTAGE;
        uint32_t so0 = (uint32_t)((row0 * PITCH + cc0 * 8) * 2);
        uint32_t so1 = (uint32_t)((row1 * PITCH + cc0 * 8) * 2);
        size_t ga0 = (size_t)(bm0 + row0) * K + k0 + cc0 * 8;
        size_t ga1 = (size_t)(bm0 + row1) * K + k0 + cc0 * 8;
        size_t gb0 = (size_t)(bn0 + row0) * K + k0 + cc0 * 8;
        size_t gb1 = (size_t)(bn0 + row1) * K + k0 + cc0 * 8;
        CP16(st + so0,          A_g + ga0);
        CP16(st + so1,          A_g + ga1);
        CP16(st + 10240 + so0,  B_g + gb0);
        CP16(st + 10240 + so1,  B_g + gb1);
    };

    issue_tile(0, 0);
    asm volatile("cp.async.commit_group;");
    issue_tile(1, 32);
    asm volatile("cp.async.commit_group;");
    issue_tile(2, 64);
    asm volatile("cp.async.commit_group;");

    int ktiles = K >> 5;
#pragma unroll 1
    for (int t = 0; t < ktiles; t++) {
        int s = t % 3;
        asm volatile("cp.async.wait_group 2;");
        __syncthreads();

        uint32_t pA = smBase + (uint32_t)s * (uint32_t)GSTAGE;
        uint32_t pB = pA + 10240u;
#pragma unroll
        for (int ks = 0; ks < 2; ks++) {
            uint32_t kb = (uint32_t)(ks * 32);
            uint32_t ah[2][4];
#pragma unroll
            for (int mi = 0; mi < 2; mi++) {
                uint32_t off = aOffH + (uint32_t)(mi * 16 * PITCH * 2) + kb;
                ldsm4(pA + off, ah[mi][0], ah[mi][1], ah[mi][2], ah[mi][3]);
            }
#pragma unroll
            for (int bp = 0; bp < 4; bp++) {
                uint32_t off = bOffH + (uint32_t)(bp * 16 * PITCH * 2) + kb;
                uint32_t bh[2][2];
                ldsm4(pB + off, bh[0][0], bh[0][1], bh[1][0], bh[1][1]);
#pragma unroll
                for (int mi = 0; mi < 2; mi++)
#pragma unroll
                    for (int q = 0; q < 2; q++)
                        mma16816(acc[mi][2 * bp + q], ah[mi], bh[q]);
            }
        }
        __syncthreads();
        int nk = (t + 3) << 5;
        if (nk < K) issue_tile(s, nk);
        asm volatile("cp.async.commit_group;");
    }

    // epilogue
    int qr = lane >> 2, qc = (lane & 3) << 1;
#pragma unroll
    for (int mi = 0; mi < 2; mi++) {
        int m0 = bm0 + wm * 32 + mi * 16 + qr;
#pragma unroll
        for (int ni = 0; ni < 8; ni++) {
            int n = bn0 + wn * 64 + ni * 8 + qc;
            float b0 = bias[n], b1 = bias[n + 1];
#pragma unroll
            for (int rr = 0; rr < 2; rr++) {
                int m = m0 + rr * 8;
                float v0 = acc[mi][ni][rr * 2 + 0] + b0;
                float v1 = acc[mi][ni][rr * 2 + 1] + b1;
                if (EPI == 1 || EPI == 3) {
                    v0 += res[(size_t)m * Nout + n];
                    v1 += res[(size_t)m * Nout + n + 1];
                }
                if (EPI == 2) {
                    v0 = v0 / (1.f + expf(-v0));
                    v1 = v1 / (1.f + expf(-v1));
                    *(__half2*)(Ch + (size_t)m * Nout + n) =
                        __half2(__float2half_rn(v0), __float2half_rn(v1));
                } else {
                    if (EPI == 3) { float rsc = rowscale[m]; v0 *= rsc; v1 *= rsc; }
                    *(float2*)(C + (size_t)m * Nout + n) = make_float2(v0, v1);
                }
            }
        }
    }
}

template<int EPI>
__global__ void __launch_bounds__(256, 2)
gemm_h(const __half* __restrict__ A_g, const __half* __restrict__ B_g,
       const float* __restrict__ bias, const float* __restrict__ res,
       const float* __restrict__ rowscale, float* __restrict__ C,
       __half* __restrict__ Ch, int M, int Nout, int K) {
    gemm_body<EPI>(A_g, B_g, bias, res, rowscale, C, Ch,
                   M, Nout, K, blockIdx.y * 128, blockIdx.x * 128);
}

// fused QKV: grid (12, 64)
__global__ void __launch_bounds__(256, 2)
gemm_qkv(const __half* __restrict__ A_g,
         const __half* __restrict__ wq, const __half* __restrict__ wk,
         const __half* __restrict__ wv,
         const float* __restrict__ bq, const float* __restrict__ bk,
         const float* __restrict__ bv,
         float* __restrict__ q, float* __restrict__ k, float* __restrict__ v) {
    int wsel = blockIdx.x >> 2;
    int bn0  = (blockIdx.x & 3) * 128;
    const __half* B;
    const float* bias;
    float* C;
    if (wsel == 0)      { B = wq; bias = bq; C = q; }
    else if (wsel == 1) { B = wk; bias = bk; C = k; }
    else                { B = wv; bias = bv; C = v; }
    gemm_body<0>(A_g, B, bias, nullptr, nullptr, C, nullptr,
                 BNROWS, DD, DD, blockIdx.y * 128, bn0);
}

// ---------------- Edge bias: one warp per 4 edges (amortize weight reads) ----------------
__global__ void edge_bias_kernel(const float* __restrict__ rel, const float* __restrict__ geo,
                                 const float* __restrict__ W_eb, const float* __restrict__ b_eb,
                                 const float* __restrict__ geog, const float* __restrict__ geob,
                                 const float* __restrict__ W_geo, const float* __restrict__ b_geo) {
    int warp = (blockIdx.x * blockDim.x + threadIdx.x) >> 5;   // 0 .. B*E/4-1
    int lane = threadIdx.x & 31;
    int e0 = warp << 2;                                        // first of 4 edges
    if (e0 >= BB * EE) return;

    const float* re = rel + (size_t)e0 * EDIM;
    const float* ge = geo + (size_t)e0 * GDIM;

    float acc[4][8];
#pragma unroll
    for (int e = 0; e < 4; e++)
#pragma unroll
        for (int h = 0; h < 8; h++) acc[e][h] = 0.f;

    // edge-embedding projection: weight loads shared across 4 edges
#pragma unroll
    for (int it = 0; it < 8; it++) {
        int c = (it << 5) + lane;
        float xv[4];
#pragma unroll
        for (int e = 0; e < 4; e++) xv[e] = re[(size_t)e * EDIM + c];
#pragma unroll
        for (int h = 0; h < 8; h++) {
            float w = W_eb[h * EDIM + c];
#pragma unroll
            for (int e = 0; e < 4; e++) acc[e][h] += xv[e] * w;
        }
    }

    // geo LN + projection per edge
    float n0[4], n1[4];
#pragma unroll
    for (int e = 0; e < 4; e++) {
        float gA = ge[(size_t)e * GDIM + lane];
        float gB = ge[(size_t)e * GDIM + lane + 32];
        float s = gA + gB, s2 = gA * gA + gB * gB;
        for (int o = 16; o; o >>= 1) {
            s  += __shfl_xor_sync(~0u, s,  o);
            s2 += __shfl_xor_sync(~0u, s2, o);
        }
        float mean = s * (1.f / 64.f);
        float var  = s2 * (1.f / 64.f) - mean * mean;
        float r = rsqrtf(var + 1e-5f);
        n0[e] = (gA - mean) * r * geog[lane]      + geob[lane];
        n1[e] = (gB - mean) * r * geog[lane + 32] + geob[lane + 32];
    }
#pragma unroll
    for (int h = 0; h < 8; h++) {
        float wA = W_geo[h * GDIM + lane];
        float wB = W_geo[h * GDIM + lane + 32];
#pragma unroll
        for (int e = 0; e < 4; e++) acc[e][h] += n0[e] * wA + n1[e] * wB;
    }

    // reduce + write
#pragma unroll
    for (int h = 0; h < 8; h++) {
#pragma unroll
        for (int e = 0; e < 4; e++) {
            float v = acc[e][h];
            for (int o = 16; o; o >>= 1) v += __shfl_xor_sync(~0u, v, o);
            if (lane == ((h << 2) | e) % 32 && lane == ((h << 2) | e))
                ;  // placeholder (write below)
            if (lane == 0) g_ebias[((size_t)e0 + e) * HH + h] = v + b_eb[h] + b_geo[h];
        }
    }
}

// ---------------- winner map + scatter ----------------
__global__ void wmap_init_kernel() {
    int idx = blockIdx.x * 256 + threadIdx.x;
    g_wmap[idx] = -1;
}

__global__ void wmap_scatter_kernel(const int* __restrict__ edges, const float* __restrict__ emask) {
    int t = blockIdx.x * 256 + threadIdx.x;
    if (t >= BB * EE) return;
    int b = t >> 10, e = t & 1023;
    if (emask[t] > 0.5f) {
        int s = min(max(edges[2 * t], 0), NNODE - 1);
        int d = min(max(edges[2 * t + 1], 0), NNODE - 1);
        atomicMax(&g_wmap[b * 65536 + s * 256 + d], e);
        atomicMax(&g_wmap[b * 65536 + d * 256 + s], e + EE);
    }
}

// ---------------- neighbor-list compaction: one warp per (b,i) ----------------
__global__ void nbr_kernel(const float* __restrict__ nmask) {
    int gw = (blockIdx.x * blockDim.x + threadIdx.x) >> 5;
    int lane = threadIdx.x & 31;
    if (gw >= BB * NNODE) return;
    int b = gw >> 8, i = gw & 255;
    if (nmask[gw] == 0.f) {
        if (lane == 0) g_cnt[gw] = 0;
        return;
    }
    const int* wrow = g_wmap + (size_t)gw * 256;
    int* nrow = g_nbr + (size_t)gw * 256;
    int base = 0;
#pragma unroll
    for (int c = 0; c < 8; c++) {
        int j = c * 32 + lane;
        int w = wrow[j];
        bool valid = ((w >= 0) || (j == i)) && (nmask[b * 256 + j] != 0.f);
        unsigned m = __ballot_sync(~0u, valid);
        if (valid) {
            int pos = base + __popc(m & ((1u << lane) - 1));
            nrow[pos] = ((w + 1) << 8) | j;
        }
        base += __popc(m);
    }
    if (lane == 0) g_cnt[gw] = base;
}

// ---------------- sparse attention: block per (b,i), warp per head ----------------
__global__ void __launch_bounds__(256)
attn_sparse_kernel() {
    __shared__ float sc[HH][NNODE];
    __shared__ float qs[HH][64];

    int bi = blockIdx.x;
    int b = bi >> 8;
    int tid = threadIdx.x, h = tid >> 5, lane = tid & 31;
    size_t orow = (size_t)bi * DD + h * HDIM;

    int cnt = g_cnt[bi];
    int d0 = lane << 1;
    if (cnt == 0) {
        *(__half2*)&g_att[orow + d0] = __half2(__float2half_rn(0.f), __float2half_rn(0.f));
        return;
    }

    qs[h][lane]      = g_q[orow + lane];
    qs[h][lane + 32] = g_q[orow + lane + 32];
    __syncwarp();

    const int* nrow = g_nbr + (size_t)bi * 256;
    const float* qh = qs[h];

    float mx = -FLT_MAX;
    for (int c0 = 0; c0 < cnt; c0 += 32) {
        int idx = c0 + lane;
        float s = -FLT_MAX;
        if (idx < cnt) {
            int packed = nrow[idx];
            int j = packed & 255;
            int w = (packed >> 8) - 1;
            const float* kr = g_k + (size_t)(b * NNODE + j) * DD + h * HDIM;
            float a = 0.f;
#pragma unroll
            for (int d4 = 0; d4 < 16; d4++) {
                float4 kv = *(const float4*)(kr + d4 * 4);
                a += kv.x * qh[d4 * 4] + kv.y * qh[d4 * 4 + 1]
                   + kv.z * qh[d4 * 4 + 2] + kv.w * qh[d4 * 4 + 3];
            }
            float bias = 0.f;
            if (w >= 0) {
                int e = (w >= EE) ? w - EE : w;
                bias = g_ebias[((size_t)b * EE + e) * HH + h];
            }
            s = a * 0.125f + bias;
            sc[h][idx] = s;
        }
        mx = fmaxf(mx, s);
    }
    for (int o = 16; o; o >>= 1) mx = fmaxf(mx, __shfl_xor_sync(~0u, mx, o));

    float sum = 0.f;
    for (int c0 = 0; c0 < cnt; c0 += 32) {
        int idx = c0 + lane;
        if (idx < cnt) {
            float p = expf(sc[h][idx] - mx);
            sc[h][idx] = p;
            sum += p;
        }
    }
    for (int o = 16; o; o >>= 1) sum += __shfl_xor_sync(~0u, sum, o);
    float inv = 1.f / sum;
    __syncwarp();

    float o0 = 0.f, o1 = 0.f;
    for (int idx = 0; idx < cnt; idx++) {
        int j = nrow[idx] & 255;
        float p = sc[h][idx];
        const float* vr = g_v + (size_t)(b * NNODE + j) * DD + h * HDIM;
        float2 vv = *(const float2*)(vr + d0);
        o0 += p * vv.x;
        o1 += p * vv.y;
    }
    o0 *= inv; o1 *= inv;
    *(__half2*)&g_att[orow + d0] = __half2(__float2half_rn(o0), __float2half_rn(o1));
}

// ---------------- host launcher ----------------
extern "C" void kernel_launch(void* const* d_in, const int* in_sizes, int n_in,
                              void* d_out, int out_size) {
    const float* x     = (const float*)d_in[0];
    const float* nmask = (const float*)d_in[1];
    const int*   edges = (const int*)  d_in[2];
    const float* emask = (const float*)d_in[3];
    const float* rel   = (const float*)d_in[4];
    const float* geo   = (const float*)d_in[5];
    const float* Wq = (const float*)d_in[6];  const float* bq = (const float*)d_in[7];
    const float* Wk = (const float*)d_in[8];  const float* bk = (const float*)d_in[9];
    const float* Wv = (const float*)d_in[10]; const float* bv = (const float*)d_in[11];
    const float* W_eb = (const float*)d_in[12]; const float* b_eb = (const float*)d_in[13];
    const float* geog = (const float*)d_in[14]; const float* geob = (const float*)d_in[15];
    const float* W_geo = (const float*)d_in[16]; const float* b_geo = (const float*)d_in[17];
    const float* W_out = (const float*)d_in[18]; const float* b_out = (const float*)d_in[19];
    const float* ng = (const float*)d_in[20]; const float* nb = (const float*)d_in[21];
    const float* fg = (const float*)d_in[22]; const float* fb = (const float*)d_in[23];
    const float* W1 = (const float*)d_in[24]; const float* b1 = (const float*)d_in[25];
    const float* W2 = (const float*)d_in[26]; const float* b2 = (const float*)d_in[27];
    float* out = (float*)d_out;

    float *pq, *pk, *pv, *px2;
    cudaGetSymbolAddress((void**)&pq,  g_q);
    cudaGetSymbolAddress((void**)&pk,  g_k);
    cudaGetSymbolAddress((void**)&pv,  g_v);
    cudaGetSymbolAddress((void**)&px2, g_x2);
    __half *xn, *att, *ln2, *h1;
    __half *wq, *wk, *wv, *wo, *w1, *w2;
    cudaGetSymbolAddress((void**)&xn,  g_xn);
    cudaGetSymbolAddress((void**)&att, g_att);
    cudaGetSymbolAddress((void**)&ln2, g_ln2);
    cudaGetSymbolAddress((void**)&h1,  g_h1);
    cudaGetSymbolAddress((void**)&wq, g_wq);
    cudaGetSymbolAddress((void**)&wk, g_wk);
    cudaGetSymbolAddress((void**)&wv, g_wv);
    cudaGetSymbolAddress((void**)&wo, g_wo);
    cudaGetSymbolAddress((void**)&w1, g_w1);
    cudaGetSymbolAddress((void**)&w2, g_w2);

    cudaFuncSetAttribute(gemm_qkv,  cudaFuncAttributeMaxDynamicSharedMemorySize, GSMEMB);
    cudaFuncSetAttribute(gemm_h<1>, cudaFuncAttributeMaxDynamicSharedMemorySize, GSMEMB);
    cudaFuncSetAttribute(gemm_h<2>, cudaFuncAttributeMaxDynamicSharedMemorySize, GSMEMB);
    cudaFuncSetAttribute(gemm_h<3>, cudaFuncAttributeMaxDynamicSharedMemorySize, GSMEMB);

    // 0) fused weight casts (one launch)
    CastJobs jobs;
    int wsz = DD * DD / 4, fsz = DFF * DD / 4;
    jobs.src[0] = (const float4*)Wq;    jobs.dst[0] = (__half2*)wq;
    jobs.src[1] = (const float4*)Wk;    jobs.dst[1] = (__half2*)wk;
    jobs.src[2] = (const float4*)Wv;    jobs.dst[2] = (__half2*)wv;
    jobs.src[3] = (const float4*)W_out; jobs.dst[3] = (__half2*)wo;
    jobs.src[4] = (const float4*)W1;    jobs.dst[4] = (__half2*)w1;
    jobs.src[5] = (const float4*)W2;    jobs.dst[5] = (__half2*)w2;
    jobs.cum[0] = 0;
    jobs.cum[1] = wsz;      jobs.cum[2] = 2 * wsz; jobs.cum[3] = 3 * wsz;
    jobs.cum[4] = 4 * wsz;  jobs.cum[5] = 4 * wsz + fsz; jobs.cum[6] = 4 * wsz + 2 * fsz;
    cast_all_kernel<<<(jobs.cum[6] + 255) / 256, 256>>>(jobs);
    // 1) pre-LN -> fp16
    ln_h_kernel<<<BNROWS, 128>>>(x, ng, nb, xn);
    // 2) fused Q,K,V projections
    gemm_qkv<<<dim3(12, BNROWS / 128), 256, GSMEMB>>>(xn, wq, wk, wv, bq, bk, bv, pq, pk, pv);
    // 3) per-edge bias (4 edges per warp)
    edge_bias_kernel<<<(BB * EE / 4) / 8, 256>>>(rel, geo, W_eb, b_eb, geog, geob, W_geo, b_geo);
    // 4) winner map + neighbor compaction
    wmap_init_kernel<<<(BB * NNODE * NNODE) / 256, 256>>>();
    wmap_scatter_kernel<<<(BB * EE) / 256, 256>>>(edges, emask);
    nbr_kernel<<<(BB * NNODE) / 8, 256>>>(nmask);
    // 5) sparse attention
    attn_sparse_kernel<<<BB * NNODE, 256>>>();
    // 6) output projection + residual
    gemm_h<1><<<dim3(DD / 128, BNROWS / 128), 256, GSMEMB>>>(att, wo, b_out, x, nullptr, px2, nullptr, BNROWS, DD, DD);
    // 7) FF block
    ln_h_kernel<<<BNROWS, 128>>>(px2, fg, fb, ln2);
    gemm_h<2><<<dim3(DFF / 128, BNROWS / 128), 256, GSMEMB>>>(ln2, w1, b1, nullptr, nullptr, nullptr, h1, BNROWS, DFF, DD);
    gemm_h<3><<<dim3(DD / 128, BNROWS / 128), 256, GSMEMB>>>(h1, w2, b2, px2, nmask, out, nullptr, BNROWS, DD, DFF);
}